// round 12
// baseline (speedup 1.0000x reference)
#include <cuda_runtime.h>
#include <cuda_fp16.h>
#include <cstdint>

// ============================================================================
// DGM cell fused kernel for plain sm_103 (no tcgen05 on this ptxas target).
// mma.sync.m16n8k16 (HMMA) + ldmatrix + cp.async.bulk.
// B=262144, D_IN=8, H=128, N_LAYERS=3, D_OUT=1.
//
// R12 = R11 (430.6us) + merged Z||G k-loop using the SAME per-gate images
// and the SAME 2-slot ring (Z resident in slot0, G in slot1):
//  * One k-loop loads each A-fragment once and feeds both Z and G MMAs:
//    A-ldsm per layer 72 -> 54 x4 ops/warp (L1 was 84.6%, the wall).
//  * Loads: after ZG consumed -> R->s0, H->s1 (hidden under ZG epilogue);
//    after R consumed -> Z(L+1)->s0 (long distance); after H -> G(L+1)->s1.
//  * Plain C++ __half2 epilogues (R10 lesson: no asm-volatile lds/sts).
//  * Parities role-constant (2 loads/slot/layer): full Z/G=0, R/H=1.
//
// CTA: 64 rows, 256 threads (8 warps). Warp w: rows m0=(w&1)*32,
// cols n0=(w>>1)*32. A tile [64][152 halves]: sigS 0..127, x 128..135,
// 1 @136, 0 @137..143. Gate = K=144 MMA chain (x@U + bias folded in).
// ============================================================================

#define GATE_HALVES (144 * 136)
#define GATE_BYTES  39168u
#define IMG_TOTAL   (12u * GATE_BYTES)

__device__ __align__(1024) unsigned char g_wimg[IMG_TOTAL];

// ---------------- smem layout (bytes) ----------------
#define OFF_MBAR  0u        // 2 full mbarriers
#define OFF_CONS  16u       // 2 consumed mbarriers
#define OFF_OUTS  64u       // 64 f32
#define OFF_WF    320u      // 129 f32 (Wf + bias)
#define OFF_SW    896u      // 8*128 f32
#define OFF_SWB   4992u     // 128 f32
#define OFF_A     5504u     // 64*304 B = 19456 (stride 152 halves)
#define OFF_SLOT0 25600u    // 39168
#define OFF_SLOT1 64768u    // 39168
#define SMEM_TOTAL 103936u

// ---------------- PTX helpers ----------------
__device__ __forceinline__ uint32_t smem_to_u32(const void* p) {
    uint32_t a;
    asm("{ .reg .u64 t; cvta.to.shared.u64 t, %1; cvt.u32.u64 %0, t; }" : "=r"(a) : "l"(p));
    return a;
}

#define MBARRIER_INIT(addr, cnt) \
    asm volatile("mbarrier.init.shared.b64 [%0], %1;" :: "r"((uint32_t)(addr)), "r"((uint32_t)(cnt)) : "memory")

#define MBARRIER_EXPECT_TX(addr, bytes) \
    asm volatile("mbarrier.arrive.expect_tx.shared.b64 _, [%0], %1;" \
        :: "r"((uint32_t)(addr)), "r"((uint32_t)(bytes)) : "memory")

#define MBARRIER_ARRIVE(addr) \
    asm volatile("mbarrier.arrive.shared.b64 _, [%0];" :: "r"((uint32_t)(addr)) : "memory")

#define MBARRIER_WAIT_PARITY(mbar_smem_addr, phase_parity) do { \
    uint32_t _mbar = (uint32_t)(mbar_smem_addr); \
    uint32_t _parity = (uint32_t)(phase_parity); \
    uint32_t _done; \
    asm volatile("{\n\t.reg .pred p;\n\t" \
        "mbarrier.try_wait.parity.acquire.cta.shared::cta.b64 p, [%1], %2;\n\t" \
        "selp.b32 %0, 1, 0, p;\n\t}" \
        : "=r"(_done) : "r"(_mbar), "r"(_parity) : "memory"); \
    if (!_done) { \
        asm volatile("{\n\t.reg .pred P1;\n\t" \
            "WAIT_LOOP_%=:\n\t" \
            "mbarrier.try_wait.parity.acquire.cta.shared::cta.b64 P1, [%0], %1, 0x989680;\n\t" \
            "@P1 bra.uni WAIT_DONE_%=;\n\t" \
            "bra.uni WAIT_LOOP_%=;\n\t" \
            "WAIT_DONE_%=:\n\t}" \
            :: "r"(_mbar), "r"(_parity) : "memory"); \
    } \
} while(0)

__device__ __forceinline__ void mbarrier_inval(uint32_t a) {
    asm volatile("mbarrier.inval.shared.b64 [%0];" :: "r"(a) : "memory");
}

__device__ __forceinline__ void bulk_g2s(uint32_t dst, const void* src,
                                         uint32_t bytes, uint32_t mbar) {
    asm volatile(
        "cp.async.bulk.shared::cluster.global.mbarrier::complete_tx::bytes "
        "[%0], [%1], %2, [%3];"
        :: "r"(dst), "l"(src), "r"(bytes), "r"(mbar) : "memory");
}

// half-CTA barrier for one m-group (4 warps = 128 threads), ids 1 and 2
#define GROUP_BAR(grp) \
    asm volatile("bar.sync %0, %1;" :: "r"((grp) + 1), "r"(128) : "memory")

__device__ __forceinline__ void ldsm4(uint32_t* r, uint32_t a) {
    asm volatile("ldmatrix.sync.aligned.m8n8.x4.shared.b16 {%0,%1,%2,%3}, [%4];"
        : "=r"(r[0]), "=r"(r[1]), "=r"(r[2]), "=r"(r[3]) : "r"(a));
}
__device__ __forceinline__ void ldsm4t(uint32_t* r, uint32_t a) {
    asm volatile("ldmatrix.sync.aligned.m8n8.x4.trans.shared.b16 {%0,%1,%2,%3}, [%4];"
        : "=r"(r[0]), "=r"(r[1]), "=r"(r[2]), "=r"(r[3]) : "r"(a));
}

__device__ __forceinline__ void mma16816(float* d, const uint32_t* a, const uint32_t* b) {
    asm volatile("mma.sync.aligned.m16n8k16.row.col.f32.f16.f16.f32 "
        "{%0,%1,%2,%3}, {%4,%5,%6,%7}, {%8,%9}, {%0,%1,%2,%3};"
        : "+f"(d[0]), "+f"(d[1]), "+f"(d[2]), "+f"(d[3])
        : "r"(a[0]), "r"(a[1]), "r"(a[2]), "r"(a[3]), "r"(b[0]), "r"(b[1]));
}

// ---------------- activations ----------------
// exact-ish f32 sigmoid (2 MUFU): S0 prologue only
__device__ __forceinline__ float sigf(float v) {
    float e, r;
    asm("ex2.approx.f32 %0, %1;" : "=f"(e) : "f"(-1.4426950408889634f * v));
    asm("rcp.approx.f32 %0, %1;" : "=f"(r) : "f"(1.0f + e));
    return r;
}
// 1-MUFU f32 tanh (err ~1e-4, damped by (1-G)) for H
__device__ __forceinline__ float tanhf1(float v) {
    float y; asm("tanh.approx.f32 %0, %1;" : "=f"(y) : "f"(v)); return y;
}
// f16x2 sigmoid: sigma(x) = 0.5*tanh(x/2) + 0.5  (1 MUFU per 2 values)
__device__ __forceinline__ __half2 sig_h2(__half2 v) {
    const __half2 h05 = __half2half2(__float2half_rn(0.5f));
    __half2 xh = __hmul2(v, h05);
    uint32_t t;
    asm("tanh.approx.f16x2 %0, %1;" : "=r"(t) : "r"(*(uint32_t*)&xh));
    return __hfma2(*(__half2*)&t, h05, h05);
}
__device__ __forceinline__ uint32_t h2u(__half2 h) { return *(uint32_t*)&h; }
__device__ __forceinline__ __half2 u2h(uint32_t u) { return *(__half2*)&u; }

// ============================================================================
// prep kernel: fp16 B images. img[G][k][n], stride 136 halves.
// gate order per layer: Z, G, R, H. k<128: W[L][k][n]; 128..135: U; 136: b.
// ============================================================================
__global__ void prep_kernel(
    const float* __restrict__ Uz, const float* __restrict__ Wz, const float* __restrict__ bz,
    const float* __restrict__ Ug, const float* __restrict__ Wg, const float* __restrict__ bg,
    const float* __restrict__ Ur, const float* __restrict__ Wr, const float* __restrict__ br,
    const float* __restrict__ Uh, const float* __restrict__ Wh, const float* __restrict__ bh)
{
    int t = blockIdx.x * blockDim.x + threadIdx.x;
    if (t >= 12 * GATE_HALVES) return;
    int G = t / GATE_HALVES;
    int rem = t % GATE_HALVES;
    int k = rem / 136;
    int n = rem % 136;
    int L = G >> 2, g = G & 3;
    float val = 0.0f;
    if (n < 128) {
        const float* W = (g == 0) ? Wz : (g == 1) ? Wg : (g == 2) ? Wr : Wh;
        const float* U = (g == 0) ? Uz : (g == 1) ? Ug : (g == 2) ? Ur : Uh;
        const float* bb = (g == 0) ? bz : (g == 1) ? bg : (g == 2) ? br : bh;
        if (k < 128)       val = W[L * 16384 + k * 128 + n];
        else if (k < 136)  val = U[L * 1024 + (k - 128) * 128 + n];
        else if (k == 136) val = bb[L * 128 + n];
    }
    *reinterpret_cast<__half*>(g_wimg + (size_t)G * GATE_BYTES + (size_t)k * 272 + (size_t)n * 2)
        = __float2half_rn(val);
}

// ============================================================================
// main fused kernel: 4096 CTAs x 256 threads, 2 CTAs/SM
// ============================================================================
__global__ void __launch_bounds__(256, 2)
dgm_kernel(const float* __restrict__ x,
           const float* __restrict__ Sw_w, const float* __restrict__ Sw_b,
           const float* __restrict__ Wf_w, const float* __restrict__ Wf_b,
           float* __restrict__ out)
{
    extern __shared__ __align__(1024) char smem[];
    const uint32_t sb = smem_to_u32(smem);
    const int tid  = threadIdx.x;
    const int lane = tid & 31;
    const int wid  = tid >> 5;
    const int mgrp = wid & 1;
    const int m0 = mgrp * 32;
    const int n0 = (wid >> 1) * 32;

    float* outs = (float*)(smem + OFF_OUTS);
    float* wf   = (float*)(smem + OFF_WF);
    float* sw   = (float*)(smem + OFF_SW);
    float* swb  = (float*)(smem + OFF_SWB);

    if (tid == 0) {
        MBARRIER_INIT(sb + OFF_MBAR,     1);
        MBARRIER_INIT(sb + OFF_MBAR + 8, 1);
        MBARRIER_INIT(sb + OFF_CONS,     8);   // one arrive per warp
        MBARRIER_INIT(sb + OFF_CONS + 8, 8);
        wf[128] = Wf_b[0];
    }
    if (tid < 128) { wf[tid] = Wf_w[tid]; swb[tid] = Sw_b[tid]; }
    if (tid < 64)  outs[tid] = 0.0f;
    ((float4*)sw)[tid] = ((const float4*)Sw_w)[tid];   // 4KB
    __syncthreads();

    // prologue: Z0 -> slot0, G0 -> slot1
    if (tid == 0) {
        MBARRIER_EXPECT_TX(sb + OFF_MBAR, GATE_BYTES);
        bulk_g2s(sb + OFF_SLOT0, g_wimg, GATE_BYTES, sb + OFF_MBAR);
        MBARRIER_EXPECT_TX(sb + OFF_MBAR + 8, GATE_BYTES);
        bulk_g2s(sb + OFF_SLOT1, g_wimg + GATE_BYTES, GATE_BYTES, sb + OFF_MBAR + 8);
    }

    // ---------- S0 = sigmoid(x @ Sw + Sw_b), write A tile + ext ----------
    {
        const int r  = tid >> 2;
        const int ch = tid & 3;
        const float* xr = x + ((size_t)blockIdx.x * 64 + r) * 8;
        float4 xa = *(const float4*)xr;
        float4 xb = *(const float4*)(xr + 4);
        char* arow = smem + OFF_A + (size_t)r * 304;
        if (ch == 0) {
            *(__half2*)(arow + (128 + 0)  * 2) = __floats2half2_rn(xa.x, xa.y);
            *(__half2*)(arow + (128 + 2)  * 2) = __floats2half2_rn(xa.z, xa.w);
            *(__half2*)(arow + (128 + 4)  * 2) = __floats2half2_rn(xb.x, xb.y);
            *(__half2*)(arow + (128 + 6)  * 2) = __floats2half2_rn(xb.z, xb.w);
            *(__half2*)(arow + (128 + 8)  * 2) = __floats2half2_rn(1.0f, 0.0f);
            *(__half2*)(arow + (128 + 10) * 2) = __floats2half2_rn(0.0f, 0.0f);
            *(__half2*)(arow + (128 + 12) * 2) = __floats2half2_rn(0.0f, 0.0f);
            *(__half2*)(arow + (128 + 14) * 2) = __floats2half2_rn(0.0f, 0.0f);
        }
#pragma unroll 4
        for (int i = 0; i < 16; i++) {
            int c = ch * 32 + 2 * i;
            float s0 = swb[c], s1 = swb[c + 1];
            s0 += xa.x * sw[0 * 128 + c] + xa.y * sw[1 * 128 + c]
                + xa.z * sw[2 * 128 + c] + xa.w * sw[3 * 128 + c]
                + xb.x * sw[4 * 128 + c] + xb.y * sw[5 * 128 + c]
                + xb.z * sw[6 * 128 + c] + xb.w * sw[7 * 128 + c];
            s1 += xa.x * sw[0 * 128 + c + 1] + xa.y * sw[1 * 128 + c + 1]
                + xa.z * sw[2 * 128 + c + 1] + xa.w * sw[3 * 128 + c + 1]
                + xb.x * sw[4 * 128 + c + 1] + xb.y * sw[5 * 128 + c + 1]
                + xb.z * sw[6 * 128 + c + 1] + xb.w * sw[7 * 128 + c + 1];
            *(__half2*)(arow + c * 2) = __floats2half2_rn(sigf(s0), sigf(s1));
        }
    }
    __syncthreads();

    // per-lane ldmatrix address bases
    const uint32_t aAddr = sb + OFF_A + (uint32_t)(m0 + (lane & 15)) * 304u
                         + (uint32_t)(lane >> 4) * 16u;
    const uint32_t bOff = (uint32_t)(lane & 15) * 272u
                        + (uint32_t)(n0 + (lane >> 4) * 8) * 2u;
    const uint32_t b0 = sb + OFF_SLOT0 + bOff;
    const uint32_t b1 = sb + OFF_SLOT1 + bOff;

    // register stage buffers: [mt*4+nt]
    uint32_t zstA[8], zstB[8], gstA[8], gstB[8];
    float pOut[2][2] = {{0.f, 0.f}, {0.f, 0.f}};

#pragma unroll 1
    for (int L = 0; L < 3; L++) {
        const unsigned char* limg = g_wimg + (size_t)L * 4 * GATE_BYTES;

        // ================= merged Z (slot0) || G (slot1) =================
        MBARRIER_WAIT_PARITY(sb + OFF_MBAR,     0);
        MBARRIER_WAIT_PARITY(sb + OFF_MBAR + 8, 0);
        {
            float accZ[2][4][4], accG[2][4][4];
#pragma unroll
            for (int i = 0; i < 2; i++)
#pragma unroll
                for (int j = 0; j < 4; j++)
#pragma unroll
                    for (int v = 0; v < 4; v++) { accZ[i][j][v] = 0.0f; accG[i][j][v] = 0.0f; }

#pragma unroll
            for (int ks = 0; ks < 9; ks++) {
                uint32_t a0[4], a1[4];
                ldsm4(a0, aAddr + (uint32_t)ks * 32u);
                ldsm4(a1, aAddr + 16u * 304u + (uint32_t)ks * 32u);
#pragma unroll
                for (int p = 0; p < 2; p++) {
                    uint32_t b[4];
                    ldsm4t(b, b0 + (uint32_t)ks * 4352u + (uint32_t)p * 32u);
                    mma16816(accZ[0][2 * p],     a0, b);
                    mma16816(accZ[0][2 * p + 1], a0, b + 2);
                    mma16816(accZ[1][2 * p],     a1, b);
                    mma16816(accZ[1][2 * p + 1], a1, b + 2);
                }
#pragma unroll
                for (int p = 0; p < 2; p++) {
                    uint32_t b[4];
                    ldsm4t(b, b1 + (uint32_t)ks * 4352u + (uint32_t)p * 32u);
                    mma16816(accG[0][2 * p],     a0, b);
                    mma16816(accG[0][2 * p + 1], a0, b + 2);
                    mma16816(accG[1][2 * p],     a1, b);
                    mma16816(accG[1][2 * p + 1], a1, b + 2);
                }
            }
            __syncwarp();
            if (lane == 0) { MBARRIER_ARRIVE(sb + OFF_CONS); MBARRIER_ARRIVE(sb + OFF_CONS + 8); }
            // both slots consumed -> load R->s0, H->s1 (hidden under ZG epilogue)
            if (tid == 0) {
                MBARRIER_WAIT_PARITY(sb + OFF_CONS, 0);
                MBARRIER_EXPECT_TX(sb + OFF_MBAR, GATE_BYTES);
                bulk_g2s(sb + OFF_SLOT0, limg + 2u * GATE_BYTES, GATE_BYTES, sb + OFF_MBAR);
                MBARRIER_WAIT_PARITY(sb + OFF_CONS + 8, 0);
                MBARRIER_EXPECT_TX(sb + OFF_MBAR + 8, GATE_BYTES);
                bulk_g2s(sb + OFF_SLOT1, limg + 3u * GATE_BYTES, GATE_BYTES, sb + OFF_MBAR + 8);
            }
            // ZG epilogue (no A writes, no barriers)
#pragma unroll
            for (int mt = 0; mt < 2; mt++) {
#pragma unroll
                for (int nt = 0; nt < 4; nt++) {
                    const int idx  = mt * 4 + nt;
                    const int rowA = m0 + mt * 16 + (lane >> 2);
                    const int col  = n0 + nt * 8 + (lane & 3) * 2;
                    char* aA = smem + OFF_A + (size_t)rowA * 304 + (size_t)col * 2;
                    char* aB = aA + 8 * 304;
                    __half2 sA = *(__half2*)aA, sB = *(__half2*)aB;
                    float* az0 = accZ[mt][nt];
                    float* ag0 = accG[mt][nt];
                    zstA[idx] = h2u(__hmul2(sig_h2(__floats2half2_rn(az0[0], az0[1])), sA));
                    zstB[idx] = h2u(__hmul2(sig_h2(__floats2half2_rn(az0[2], az0[3])), sB));
                    gstA[idx] = h2u(sig_h2(__floats2half2_rn(ag0[0], ag0[1])));
                    gstB[idx] = h2u(sig_h2(__floats2half2_rn(ag0[2], ag0[3])));
                }
            }
        }

        // ================= R gate (slot0) =================
        MBARRIER_WAIT_PARITY(sb + OFF_MBAR, 1);
        {
            float acc[2][4][4];
#pragma unroll
            for (int i = 0; i < 2; i++)
#pragma unroll
                for (int j = 0; j < 4; j++)
#pragma unroll
                    for (int v = 0; v < 4; v++) acc[i][j][v] = 0.0f;

#pragma unroll
            for (int ks = 0; ks < 9; ks++) {
                uint32_t a0[4], a1[4];
                ldsm4(a0, aAddr + (uint32_t)ks * 32u);
                ldsm4(a1, aAddr + 16u * 304u + (uint32_t)ks * 32u);
#pragma unroll
                for (int p = 0; p < 2; p++) {
                    uint32_t b[4];
                    ldsm4t(b, b0 + (uint32_t)ks * 4352u + (uint32_t)p * 32u);
                    mma16816(acc[0][2 * p],     a0, b);
                    mma16816(acc[0][2 * p + 1], a0, b + 2);
                    mma16816(acc[1][2 * p],     a1, b);
                    mma16816(acc[1][2 * p + 1], a1, b + 2);
                }
            }
            __syncwarp();
            if (lane == 0) MBARRIER_ARRIVE(sb + OFF_CONS);
            // R consumed -> load next layer's Z into slot0 (long distance)
            if (tid == 0 && L < 2) {
                MBARRIER_WAIT_PARITY(sb + OFF_CONS, 1);
                MBARRIER_EXPECT_TX(sb + OFF_MBAR, GATE_BYTES);
                bulk_g2s(sb + OFF_SLOT0, limg + 4u * GATE_BYTES, GATE_BYTES, sb + OFF_MBAR);
            }
            // A <- sigS * sig(R)
            GROUP_BAR(mgrp);
#pragma unroll
            for (int mt = 0; mt < 2; mt++) {
#pragma unroll
                for (int nt = 0; nt < 4; nt++) {
                    const int rowA = m0 + mt * 16 + (lane >> 2);
                    const int col  = n0 + nt * 8 + (lane & 3) * 2;
                    char* aA = smem + OFF_A + (size_t)rowA * 304 + (size_t)col * 2;
                    char* aB = aA + 8 * 304;
                    float* a4 = acc[mt][nt];
                    __half2 sA = *(__half2*)aA, sB = *(__half2*)aB;
                    *(__half2*)aA = __hmul2(sig_h2(__floats2half2_rn(a4[0], a4[1])), sA);
                    *(__half2*)aB = __hmul2(sig_h2(__floats2half2_rn(a4[2], a4[3])), sB);
                }
            }
            GROUP_BAR(mgrp);
        }

        // ================= H gate (slot1) =================
        MBARRIER_WAIT_PARITY(sb + OFF_MBAR + 8, 1);
        {
            float acc[2][4][4];
#pragma unroll
            for (int i = 0; i < 2; i++)
#pragma unroll
                for (int j = 0; j < 4; j++)
#pragma unroll
                    for (int v = 0; v < 4; v++) acc[i][j][v] = 0.0f;

#pragma unroll
            for (int ks = 0; ks < 9; ks++) {
                uint32_t a0[4], a1[4];
                ldsm4(a0, aAddr + (uint32_t)ks * 32u);
                ldsm4(a1, aAddr + 16u * 304u + (uint32_t)ks * 32u);
#pragma unroll
                for (int p = 0; p < 2; p++) {
                    uint32_t b[4];
                    ldsm4t(b, b1 + (uint32_t)ks * 4352u + (uint32_t)p * 32u);
                    mma16816(acc[0][2 * p],     a0, b);
                    mma16816(acc[0][2 * p + 1], a0, b + 2);
                    mma16816(acc[1][2 * p],     a1, b);
                    mma16816(acc[1][2 * p + 1], a1, b + 2);
                }
            }
            __syncwarp();
            if (lane == 0) MBARRIER_ARRIVE(sb + OFF_CONS + 8);
            // H consumed -> load next layer's G into slot1
            if (tid == 0 && L < 2) {
                MBARRIER_WAIT_PARITY(sb + OFF_CONS + 8, 1);
                MBARRIER_EXPECT_TX(sb + OFF_MBAR + 8, GATE_BYTES);
                bulk_g2s(sb + OFF_SLOT1, limg + 5u * GATE_BYTES, GATE_BYTES, sb + OFF_MBAR + 8);
            }

            const bool last = (L == 2);
            if (!last) GROUP_BAR(mgrp);
#pragma unroll
            for (int mt = 0; mt < 2; mt++) {
#pragma unroll
                for (int nt = 0; nt < 4; nt++) {
                    const int idx  = mt * 4 + nt;
                    const int rowA = m0 + mt * 16 + (lane >> 2);
                    const int col  = n0 + nt * 8 + (lane & 3) * 2;
                    char* aA = smem + OFF_A + (size_t)rowA * 304 + (size_t)col * 2;
                    char* aB = aA + 8 * 304;
                    float* a4 = acc[mt][nt];
                    __half2 zzA = u2h(zstA[idx]), zzB = u2h(zstB[idx]);
                    __half2 ggA = u2h(gstA[idx]), ggB = u2h(gstB[idx]);
                    float sp0 = (1.0f - __low2float(ggA))  * tanhf1(a4[0]) + __low2float(zzA);
                    float sp1 = (1.0f - __high2float(ggA)) * tanhf1(a4[1]) + __high2float(zzA);
                    float sp2 = (1.0f - __low2float(ggB))  * tanhf1(a4[2]) + __low2float(zzB);
                    float sp3 = (1.0f - __high2float(ggB)) * tanhf1(a4[3]) + __high2float(zzB);
                    if (!last) {
                        *(__half2*)aA = sig_h2(__floats2half2_rn(sp0, sp1));
                        *(__half2*)aB = sig_h2(__floats2half2_rn(sp2, sp3));
                    } else {
                        pOut[mt][0] += sp0 * wf[col] + sp1 * wf[col + 1];
                        pOut[mt][1] += sp2 * wf[col] + sp3 * wf[col + 1];
                    }
                }
            }
            if (!last) GROUP_BAR(mgrp);
        }
    }

    // ---------------- final reduction: out = S' @ Wf + b ----------------
#pragma unroll
    for (int mt = 0; mt < 2; mt++) {
#pragma unroll
        for (int ab = 0; ab < 2; ab++) {
            float v = pOut[mt][ab];
            v += __shfl_xor_sync(0xffffffffu, v, 1);
            v += __shfl_xor_sync(0xffffffffu, v, 2);
            if ((lane & 3) == 0) {
                int row = m0 + mt * 16 + (lane >> 2) + ab * 8;
                atomicAdd(outs + row, v);
            }
        }
    }
    __syncthreads();
    if (tid < 64)
        out[(size_t)blockIdx.x * 64 + tid] = outs[tid] + wf[128];

    if (tid == 0) {
        mbarrier_inval(sb + OFF_MBAR);
        mbarrier_inval(sb + OFF_MBAR + 8);
        mbarrier_inval(sb + OFF_CONS);
        mbarrier_inval(sb + OFF_CONS + 8);
    }
}

// ============================================================================
extern "C" void kernel_launch(void* const* d_in, const int* in_sizes, int n_in,
                              void* d_out, int out_size) {
    (void)in_sizes; (void)n_in; (void)out_size;
    const float* x     = (const float*)d_in[0];
    const float* Sw_w  = (const float*)d_in[1];
    const float* Sw_b  = (const float*)d_in[2];
    const float* Uz    = (const float*)d_in[3];
    const float* Wsz_w = (const float*)d_in[4];
    const float* Wsz_b = (const float*)d_in[5];
    const float* Ug    = (const float*)d_in[6];
    const float* Wsg_w = (const float*)d_in[7];
    const float* Wsg_b = (const float*)d_in[8];
    const float* Ur    = (const float*)d_in[9];
    const float* Wsr_w = (const float*)d_in[10];
    const float* Wsr_b = (const float*)d_in[11];
    const float* Uh    = (const float*)d_in[12];
    const float* Wsh_w = (const float*)d_in[13];
    const float* Wsh_b = (const float*)d_in[14];
    const float* Wf_w  = (const float*)d_in[15];
    const float* Wf_b  = (const float*)d_in[16];
    float* out = (float*)d_out;

    cudaFuncSetAttribute(dgm_kernel, cudaFuncAttributeMaxDynamicSharedMemorySize,
                         SMEM_TOTAL);

    prep_kernel<<<918, 256>>>(Uz, Wsz_w, Wsz_b, Ug, Wsg_w, Wsg_b,
                              Ur, Wsr_w, Wsr_b, Uh, Wsh_w, Wsh_b);
    dgm_kernel<<<4096, 256, SMEM_TOTAL>>>(x, Sw_w, Sw_b, Wf_w, Wf_b, out);
}

// round 13
// speedup vs baseline: 1.2932x; 1.2932x over previous
#include <cuda_runtime.h>
#include <cuda_fp16.h>
#include <cstdint>

// ============================================================================
// DGM cell fused kernel for plain sm_103 (no tcgen05 on this ptxas target).
// mma.sync.m16n8k16 (HMMA) + ldmatrix + cp.async.bulk.
// B=262144, D_IN=8, H=128, N_LAYERS=3, D_OUT=1.
//
// R13 = R11 (430.6us, best) + ONE delta:
//  * S0 prologue remap: r = tid&63, ch = tid>>6 (was r=tid>>2, ch=tid&3).
//    All lanes of a warp now share ch -> every sw/swb LDS is a broadcast
//    (1 wavefront, was a 4-way bank conflict = 4 wavefronts: addresses 32
//    words apart across lanes hit the same bank). x loads become
//    lane-consecutive -> fully coalesced. ~6K smem wavefronts/CTA saved.
//  (R12's merged ZG k-loop cut L1 busy but lost more to bunched weight-load
//   exposure; reverted. Merged-gate designs closed: R6/R9/R12 all net-lose.)
//
// CTA: 64 rows, 256 threads (8 warps). Warp w: rows m0=(w&1)*32,
// cols n0=(w>>1)*32. acc = 2x4 m16n8 tiles (32 fp32 regs).
// A tile (SMEM): [64 rows][152 halves]: sigS 0..127, x 128..135, 1 @136,
// 0 @137..143. Gate = one K=144 MMA chain (x@U + bias folded in).
// B images: [144][136] fp16 per gate, 2-slot ring, prefetch depth 2,
// consumed-mbarrier recycling, m-group-local named barriers.
// ============================================================================

#define GATE_HALVES (144 * 136)
#define GATE_BYTES  39168u
#define IMG_TOTAL   (12u * GATE_BYTES)

__device__ __align__(1024) unsigned char g_wimg[IMG_TOTAL];

// ---------------- smem layout (bytes) ----------------
#define OFF_MBAR  0u        // 2 full mbarriers
#define OFF_CONS  16u       // 2 consumed mbarriers
#define OFF_OUTS  64u       // 64 f32
#define OFF_WF    320u      // 129 f32 (Wf + bias)
#define OFF_SW    896u      // 8*128 f32
#define OFF_SWB   4992u     // 128 f32
#define OFF_A     5504u     // 64*304 B = 19456 (stride 152 halves)
#define OFF_SLOT0 25600u    // 39168
#define OFF_SLOT1 64768u    // 39168
#define SMEM_TOTAL 103936u

// ---------------- PTX helpers ----------------
__device__ __forceinline__ uint32_t smem_to_u32(const void* p) {
    uint32_t a;
    asm("{ .reg .u64 t; cvta.to.shared.u64 t, %1; cvt.u32.u64 %0, t; }" : "=r"(a) : "l"(p));
    return a;
}

#define MBARRIER_INIT(addr, cnt) \
    asm volatile("mbarrier.init.shared.b64 [%0], %1;" :: "r"((uint32_t)(addr)), "r"((uint32_t)(cnt)) : "memory")

#define MBARRIER_EXPECT_TX(addr, bytes) \
    asm volatile("mbarrier.arrive.expect_tx.shared.b64 _, [%0], %1;" \
        :: "r"((uint32_t)(addr)), "r"((uint32_t)(bytes)) : "memory")

#define MBARRIER_ARRIVE(addr) \
    asm volatile("mbarrier.arrive.shared.b64 _, [%0];" :: "r"((uint32_t)(addr)) : "memory")

#define MBARRIER_WAIT_PARITY(mbar_smem_addr, phase_parity) do { \
    uint32_t _mbar = (uint32_t)(mbar_smem_addr); \
    uint32_t _parity = (uint32_t)(phase_parity); \
    uint32_t _done; \
    asm volatile("{\n\t.reg .pred p;\n\t" \
        "mbarrier.try_wait.parity.acquire.cta.shared::cta.b64 p, [%1], %2;\n\t" \
        "selp.b32 %0, 1, 0, p;\n\t}" \
        : "=r"(_done) : "r"(_mbar), "r"(_parity) : "memory"); \
    if (!_done) { \
        asm volatile("{\n\t.reg .pred P1;\n\t" \
            "WAIT_LOOP_%=:\n\t" \
            "mbarrier.try_wait.parity.acquire.cta.shared::cta.b64 P1, [%0], %1, 0x989680;\n\t" \
            "@P1 bra.uni WAIT_DONE_%=;\n\t" \
            "bra.uni WAIT_LOOP_%=;\n\t" \
            "WAIT_DONE_%=:\n\t}" \
            :: "r"(_mbar), "r"(_parity) : "memory"); \
    } \
} while(0)

__device__ __forceinline__ void mbarrier_inval(uint32_t a) {
    asm volatile("mbarrier.inval.shared.b64 [%0];" :: "r"(a) : "memory");
}

__device__ __forceinline__ void bulk_g2s(uint32_t dst, const void* src,
                                         uint32_t bytes, uint32_t mbar) {
    asm volatile(
        "cp.async.bulk.shared::cluster.global.mbarrier::complete_tx::bytes "
        "[%0], [%1], %2, [%3];"
        :: "r"(dst), "l"(src), "r"(bytes), "r"(mbar) : "memory");
}

// half-CTA barrier for one m-group (4 warps = 128 threads), ids 1 and 2
#define GROUP_BAR(grp) \
    asm volatile("bar.sync %0, %1;" :: "r"((grp) + 1), "r"(128) : "memory")

__device__ __forceinline__ void ldsm4(uint32_t* r, uint32_t a) {
    asm volatile("ldmatrix.sync.aligned.m8n8.x4.shared.b16 {%0,%1,%2,%3}, [%4];"
        : "=r"(r[0]), "=r"(r[1]), "=r"(r[2]), "=r"(r[3]) : "r"(a));
}
__device__ __forceinline__ void ldsm4t(uint32_t* r, uint32_t a) {
    asm volatile("ldmatrix.sync.aligned.m8n8.x4.trans.shared.b16 {%0,%1,%2,%3}, [%4];"
        : "=r"(r[0]), "=r"(r[1]), "=r"(r[2]), "=r"(r[3]) : "r"(a));
}

__device__ __forceinline__ void mma16816(float* d, const uint32_t* a, const uint32_t* b) {
    asm volatile("mma.sync.aligned.m16n8k16.row.col.f32.f16.f16.f32 "
        "{%0,%1,%2,%3}, {%4,%5,%6,%7}, {%8,%9}, {%0,%1,%2,%3};"
        : "+f"(d[0]), "+f"(d[1]), "+f"(d[2]), "+f"(d[3])
        : "r"(a[0]), "r"(a[1]), "r"(a[2]), "r"(a[3]), "r"(b[0]), "r"(b[1]));
}

// ---------------- activations ----------------
// exact-ish f32 sigmoid (2 MUFU): S0 prologue only
__device__ __forceinline__ float sigf(float v) {
    float e, r;
    asm("ex2.approx.f32 %0, %1;" : "=f"(e) : "f"(-1.4426950408889634f * v));
    asm("rcp.approx.f32 %0, %1;" : "=f"(r) : "f"(1.0f + e));
    return r;
}
// 1-MUFU f32 tanh (err ~1e-4, damped by (1-G)) for H
__device__ __forceinline__ float tanhf1(float v) {
    float y; asm("tanh.approx.f32 %0, %1;" : "=f"(y) : "f"(v)); return y;
}
// f16x2 sigmoid: sigma(x) = 0.5*tanh(x/2) + 0.5  (1 MUFU per 2 values)
__device__ __forceinline__ __half2 sig_h2(__half2 v) {
    const __half2 h05 = __half2half2(__float2half_rn(0.5f));
    __half2 xh = __hmul2(v, h05);
    uint32_t t;
    asm("tanh.approx.f16x2 %0, %1;" : "=r"(t) : "r"(*(uint32_t*)&xh));
    return __hfma2(*(__half2*)&t, h05, h05);
}
__device__ __forceinline__ uint32_t h2u(__half2 h) { return *(uint32_t*)&h; }
__device__ __forceinline__ __half2 u2h(uint32_t u) { return *(__half2*)&u; }

// ============================================================================
// prep kernel: fp16 B images. img[G][k][n], stride 136 halves.
// gate order per layer: Z, G, R, H. k<128: W[L][k][n]; 128..135: U; 136: b.
// ============================================================================
__global__ void prep_kernel(
    const float* __restrict__ Uz, const float* __restrict__ Wz, const float* __restrict__ bz,
    const float* __restrict__ Ug, const float* __restrict__ Wg, const float* __restrict__ bg,
    const float* __restrict__ Ur, const float* __restrict__ Wr, const float* __restrict__ br,
    const float* __restrict__ Uh, const float* __restrict__ Wh, const float* __restrict__ bh)
{
    int t = blockIdx.x * blockDim.x + threadIdx.x;
    if (t >= 12 * GATE_HALVES) return;
    int G = t / GATE_HALVES;
    int rem = t % GATE_HALVES;
    int k = rem / 136;
    int n = rem % 136;
    int L = G >> 2, g = G & 3;
    float val = 0.0f;
    if (n < 128) {
        const float* W = (g == 0) ? Wz : (g == 1) ? Wg : (g == 2) ? Wr : Wh;
        const float* U = (g == 0) ? Uz : (g == 1) ? Ug : (g == 2) ? Ur : Uh;
        const float* bb = (g == 0) ? bz : (g == 1) ? bg : (g == 2) ? br : bh;
        if (k < 128)       val = W[L * 16384 + k * 128 + n];
        else if (k < 136)  val = U[L * 1024 + (k - 128) * 128 + n];
        else if (k == 136) val = bb[L * 128 + n];
    }
    *reinterpret_cast<__half*>(g_wimg + (size_t)G * GATE_BYTES + (size_t)k * 272 + (size_t)n * 2)
        = __float2half_rn(val);
}

// ============================================================================
// main fused kernel: 4096 CTAs x 256 threads, 2 CTAs/SM
// ============================================================================
__global__ void __launch_bounds__(256, 2)
dgm_kernel(const float* __restrict__ x,
           const float* __restrict__ Sw_w, const float* __restrict__ Sw_b,
           const float* __restrict__ Wf_w, const float* __restrict__ Wf_b,
           float* __restrict__ out)
{
    extern __shared__ __align__(1024) char smem[];
    const uint32_t sb = smem_to_u32(smem);
    const int tid  = threadIdx.x;
    const int lane = tid & 31;
    const int wid  = tid >> 5;
    const int mgrp = wid & 1;
    const int m0 = mgrp * 32;
    const int n0 = (wid >> 1) * 32;

    float* outs = (float*)(smem + OFF_OUTS);
    float* wf   = (float*)(smem + OFF_WF);
    float* sw   = (float*)(smem + OFF_SW);
    float* swb  = (float*)(smem + OFF_SWB);

    if (tid == 0) {
        MBARRIER_INIT(sb + OFF_MBAR,     1);
        MBARRIER_INIT(sb + OFF_MBAR + 8, 1);
        MBARRIER_INIT(sb + OFF_CONS,     8);   // one arrive per warp
        MBARRIER_INIT(sb + OFF_CONS + 8, 8);
        wf[128] = Wf_b[0];
    }
    if (tid < 128) { wf[tid] = Wf_w[tid]; swb[tid] = Sw_b[tid]; }
    if (tid < 64)  outs[tid] = 0.0f;
    ((float4*)sw)[tid] = ((const float4*)Sw_w)[tid];   // 4KB
    __syncthreads();

    // kick first two gate-weight loads
    if (tid == 0) {
        MBARRIER_EXPECT_TX(sb + OFF_MBAR, GATE_BYTES);
        bulk_g2s(sb + OFF_SLOT0, g_wimg, GATE_BYTES, sb + OFF_MBAR);
        MBARRIER_EXPECT_TX(sb + OFF_MBAR + 8, GATE_BYTES);
        bulk_g2s(sb + OFF_SLOT1, g_wimg + GATE_BYTES, GATE_BYTES, sb + OFF_MBAR + 8);
    }

    // ---------- S0 = sigmoid(x @ Sw + Sw_b), write A tile + ext ----------
    // R13 remap: r = tid&63, ch = tid>>6 -> all lanes of a warp share ch, so
    // every sw/swb LDS is a 1-wavefront broadcast (was 4-way bank conflict),
    // and x loads are lane-consecutive (fully coalesced).
    {
        const int r  = tid & 63;           // 64 rows, lane-consecutive
        const int ch = tid >> 6;           // 32 cols per thread, warp-uniform
        const float* xr = x + ((size_t)blockIdx.x * 64 + r) * 8;
        float4 xa = *(const float4*)xr;
        float4 xb = *(const float4*)(xr + 4);
        char* arow = smem + OFF_A + (size_t)r * 304;
        if (ch == 0) {
            *(__half2*)(arow + (128 + 0)  * 2) = __floats2half2_rn(xa.x, xa.y);
            *(__half2*)(arow + (128 + 2)  * 2) = __floats2half2_rn(xa.z, xa.w);
            *(__half2*)(arow + (128 + 4)  * 2) = __floats2half2_rn(xb.x, xb.y);
            *(__half2*)(arow + (128 + 6)  * 2) = __floats2half2_rn(xb.z, xb.w);
            *(__half2*)(arow + (128 + 8)  * 2) = __floats2half2_rn(1.0f, 0.0f);
            *(__half2*)(arow + (128 + 10) * 2) = __floats2half2_rn(0.0f, 0.0f);
            *(__half2*)(arow + (128 + 12) * 2) = __floats2half2_rn(0.0f, 0.0f);
            *(__half2*)(arow + (128 + 14) * 2) = __floats2half2_rn(0.0f, 0.0f);
        }
#pragma unroll 4
        for (int i = 0; i < 16; i++) {
            int c = ch * 32 + 2 * i;
            float s0 = swb[c], s1 = swb[c + 1];
            s0 += xa.x * sw[0 * 128 + c] + xa.y * sw[1 * 128 + c]
                + xa.z * sw[2 * 128 + c] + xa.w * sw[3 * 128 + c]
                + xb.x * sw[4 * 128 + c] + xb.y * sw[5 * 128 + c]
                + xb.z * sw[6 * 128 + c] + xb.w * sw[7 * 128 + c];
            s1 += xa.x * sw[0 * 128 + c + 1] + xa.y * sw[1 * 128 + c + 1]
                + xa.z * sw[2 * 128 + c + 1] + xa.w * sw[3 * 128 + c + 1]
                + xb.x * sw[4 * 128 + c + 1] + xb.y * sw[5 * 128 + c + 1]
                + xb.z * sw[6 * 128 + c + 1] + xb.w * sw[7 * 128 + c + 1];
            *(__half2*)(arow + c * 2) = __floats2half2_rn(sigf(s0), sigf(s1));
        }
    }
    __syncthreads();

    // per-lane ldmatrix address bases
    const uint32_t aAddr = sb + OFF_A + (uint32_t)(m0 + (lane & 15)) * 304u
                         + (uint32_t)(lane >> 4) * 16u;
    const uint32_t bOff = (uint32_t)(lane & 15) * 272u
                        + (uint32_t)(n0 + (lane >> 4) * 8) * 2u;

    // register stage buffers: [mt*4+nt]
    uint32_t zstA[8], zstB[8], gstA[8], gstB[8];
    float pOut[2][2] = {{0.f, 0.f}, {0.f, 0.f}};

#pragma unroll 1
    for (int G = 0; G < 12; G++) {
        const int g = G & 3;
        const int L = G >> 2;
        const int slot = G & 1;
        const uint32_t slotB = sb + (slot ? OFF_SLOT1 : OFF_SLOT0);

        MBARRIER_WAIT_PARITY(sb + OFF_MBAR + slot * 8, (G >> 1) & 1);

        float acc[2][4][4];
#pragma unroll
        for (int i = 0; i < 2; i++)
#pragma unroll
            for (int j = 0; j < 4; j++)
#pragma unroll
                for (int v = 0; v < 4; v++) acc[i][j][v] = 0.0f;

#pragma unroll
        for (int ks = 0; ks < 9; ks++) {
            uint32_t a0[4], a1[4];
            ldsm4(a0, aAddr + (uint32_t)ks * 32u);
            ldsm4(a1, aAddr + 16u * 304u + (uint32_t)ks * 32u);
#pragma unroll
            for (int p = 0; p < 2; p++) {
                uint32_t b[4];
                ldsm4t(b, slotB + bOff + (uint32_t)ks * 4352u + (uint32_t)p * 32u);
                mma16816(acc[0][2 * p],     a0, b);
                mma16816(acc[0][2 * p + 1], a0, b + 2);
                mma16816(acc[1][2 * p],     a1, b);
                mma16816(acc[1][2 * p + 1], a1, b + 2);
            }
        }

        // slot consumed by this warp
        __syncwarp();
        if (lane == 0) MBARRIER_ARRIVE(sb + OFF_CONS + slot * 8);

        // producer: refill this slot with gate G+2 after all 8 warps consumed
        if (tid == 0 && G < 10) {
            MBARRIER_WAIT_PARITY(sb + OFF_CONS + slot * 8, (G >> 1) & 1);
            MBARRIER_EXPECT_TX(sb + OFF_MBAR + slot * 8, GATE_BYTES);
            bulk_g2s(slotB, g_wimg + (size_t)(G + 2) * GATE_BYTES, GATE_BYTES,
                     sb + OFF_MBAR + slot * 8);
        }

        // A-write epilogues need the m-group's A reads (MMA) finished first
        const bool writesA = (g == 2) || (g == 3 && L < 2);
        if (writesA) GROUP_BAR(mgrp);

        // ---------------- per-gate epilogue ----------------
#pragma unroll
        for (int mt = 0; mt < 2; mt++) {
#pragma unroll
            for (int nt = 0; nt < 4; nt++) {
                float* a4 = acc[mt][nt];
                const int idx  = mt * 4 + nt;
                const int rowA = m0 + mt * 16 + (lane >> 2);
                const int col  = n0 + nt * 8 + (lane & 3) * 2;
                char* aA = smem + OFF_A + (size_t)rowA * 304 + (size_t)col * 2;
                char* aB = aA + 8 * 304;

                if (g == 0) {            // zst = sig(Z) * sigS   (f16x2 path)
                    __half2 sA = *(__half2*)aA, sB = *(__half2*)aB;
                    __half2 r0 = __hmul2(sig_h2(__floats2half2_rn(a4[0], a4[1])), sA);
                    __half2 r1 = __hmul2(sig_h2(__floats2half2_rn(a4[2], a4[3])), sB);
                    zstA[idx] = h2u(r0);
                    zstB[idx] = h2u(r1);
                } else if (g == 1) {     // gst = sig(G)          (f16x2 path)
                    gstA[idx] = h2u(sig_h2(__floats2half2_rn(a4[0], a4[1])));
                    gstB[idx] = h2u(sig_h2(__floats2half2_rn(a4[2], a4[3])));
                } else if (g == 2) {     // A <- sigS * sig(R)    (f16x2 path)
                    __half2 sA = *(__half2*)aA, sB = *(__half2*)aB;
                    *(__half2*)aA = __hmul2(sig_h2(__floats2half2_rn(a4[0], a4[1])), sA);
                    *(__half2*)aB = __hmul2(sig_h2(__floats2half2_rn(a4[2], a4[3])), sB);
                } else {                 // S' = (1-sigG)*tanh(H) + z*sigS
                    __half2 zzA = u2h(zstA[idx]), zzB = u2h(zstB[idx]);
                    __half2 ggA = u2h(gstA[idx]), ggB = u2h(gstB[idx]);
                    float sp0 = (1.0f - __low2float(ggA))  * tanhf1(a4[0]) + __low2float(zzA);
                    float sp1 = (1.0f - __high2float(ggA)) * tanhf1(a4[1]) + __high2float(zzA);
                    float sp2 = (1.0f - __low2float(ggB))  * tanhf1(a4[2]) + __low2float(zzB);
                    float sp3 = (1.0f - __high2float(ggB)) * tanhf1(a4[3]) + __high2float(zzB);
                    if (L < 2) {
                        *(__half2*)aA = sig_h2(__floats2half2_rn(sp0, sp1));
                        *(__half2*)aB = sig_h2(__floats2half2_rn(sp2, sp3));
                    } else {
                        pOut[mt][0] += sp0 * wf[col] + sp1 * wf[col + 1];
                        pOut[mt][1] += sp2 * wf[col] + sp3 * wf[col + 1];
                    }
                }
            }
        }
        if (writesA) GROUP_BAR(mgrp);   // A writes visible before next MMA reads
    }

    // ---------------- final reduction: out = S' @ Wf + b ----------------
#pragma unroll
    for (int mt = 0; mt < 2; mt++) {
#pragma unroll
        for (int ab = 0; ab < 2; ab++) {
            float v = pOut[mt][ab];
            v += __shfl_xor_sync(0xffffffffu, v, 1);
            v += __shfl_xor_sync(0xffffffffu, v, 2);
            if ((lane & 3) == 0) {
                int row = m0 + mt * 16 + (lane >> 2) + ab * 8;
                atomicAdd(outs + row, v);
            }
        }
    }
    __syncthreads();
    if (tid < 64)
        out[(size_t)blockIdx.x * 64 + tid] = outs[tid] + wf[128];

    if (tid == 0) {
        mbarrier_inval(sb + OFF_MBAR);
        mbarrier_inval(sb + OFF_MBAR + 8);
        mbarrier_inval(sb + OFF_CONS);
        mbarrier_inval(sb + OFF_CONS + 8);
    }
}

// ============================================================================
extern "C" void kernel_launch(void* const* d_in, const int* in_sizes, int n_in,
                              void* d_out, int out_size) {
    (void)in_sizes; (void)n_in; (void)out_size;
    const float* x     = (const float*)d_in[0];
    const float* Sw_w  = (const float*)d_in[1];
    const float* Sw_b  = (const float*)d_in[2];
    const float* Uz    = (const float*)d_in[3];
    const float* Wsz_w = (const float*)d_in[4];
    const float* Wsz_b = (const float*)d_in[5];
    const float* Ug    = (const float*)d_in[6];
    const float* Wsg_w = (const float*)d_in[7];
    const float* Wsg_b = (const float*)d_in[8];
    const float* Ur    = (const float*)d_in[9];
    const float* Wsr_w = (const float*)d_in[10];
    const float* Wsr_b = (const float*)d_in[11];
    const float* Uh    = (const float*)d_in[12];
    const float* Wsh_w = (const float*)d_in[13];
    const float* Wsh_b = (const float*)d_in[14];
    const float* Wf_w  = (const float*)d_in[15];
    const float* Wf_b  = (const float*)d_in[16];
    float* out = (float*)d_out;

    cudaFuncSetAttribute(dgm_kernel, cudaFuncAttributeMaxDynamicSharedMemorySize,
                         SMEM_TOTAL);

    prep_kernel<<<918, 256>>>(Uz, Wsz_w, Wsz_b, Ug, Wsg_w, Wsg_b,
                              Ur, Wsr_w, Wsr_b, Uh, Wsh_w, Wsh_b);
    dgm_kernel<<<4096, 256, SMEM_TOTAL>>>(x, Sw_w, Sw_b, Wf_w, Wf_b, out);
}

// round 14
// speedup vs baseline: 1.3026x; 1.0072x over previous
#include <cuda_runtime.h>
#include <cuda_fp16.h>
#include <cstdint>

// ============================================================================
// DGM cell fused kernel for plain sm_103 (no tcgen05 on this ptxas target).
// mma.sync.m16n8k16 (HMMA) + ldmatrix + cp.async.bulk.
// B=262144, D_IN=8, H=128, N_LAYERS=3, D_OUT=1.
//
// R14 = R13 (342.4us, best) + ONE delta: epilogue critical-section slimming.
//  * All register-only math (sig_h2 of acc, tanh, S' formula) hoisted ABOVE
//    the first GROUP_BAR of the A-writing epilogues (R; H when L<2); between
//    the two barriers only the bare smem read/modify/write remains.
//    Also lets lagging warps catch up during the MUFU block -> less bar-stall.
//  (R13's prologue broadcast-remap saved ~100us of L1 busy, matching the
//   wavefront model; 32x32 warp tile proven traffic-optimal; bigger tiles
//   hit the 128-reg wall.)
//
// CTA: 64 rows, 256 threads (8 warps). Warp w: rows m0=(w&1)*32,
// cols n0=(w>>1)*32. acc = 2x4 m16n8 tiles (32 fp32 regs).
// A tile (SMEM): [64 rows][152 halves]: sigS 0..127, x 128..135, 1 @136,
// 0 @137..143. Gate = one K=144 MMA chain (x@U + bias folded in).
// B images: [144][136] fp16 per gate, 2-slot ring, prefetch depth 2,
// consumed-mbarrier recycling, m-group-local named barriers.
// ============================================================================

#define GATE_HALVES (144 * 136)
#define GATE_BYTES  39168u
#define IMG_TOTAL   (12u * GATE_BYTES)

__device__ __align__(1024) unsigned char g_wimg[IMG_TOTAL];

// ---------------- smem layout (bytes) ----------------
#define OFF_MBAR  0u        // 2 full mbarriers
#define OFF_CONS  16u       // 2 consumed mbarriers
#define OFF_OUTS  64u       // 64 f32
#define OFF_WF    320u      // 129 f32 (Wf + bias)
#define OFF_SW    896u      // 8*128 f32
#define OFF_SWB   4992u     // 128 f32
#define OFF_A     5504u     // 64*304 B = 19456 (stride 152 halves)
#define OFF_SLOT0 25600u    // 39168
#define OFF_SLOT1 64768u    // 39168
#define SMEM_TOTAL 103936u

// ---------------- PTX helpers ----------------
__device__ __forceinline__ uint32_t smem_to_u32(const void* p) {
    uint32_t a;
    asm("{ .reg .u64 t; cvta.to.shared.u64 t, %1; cvt.u32.u64 %0, t; }" : "=r"(a) : "l"(p));
    return a;
}

#define MBARRIER_INIT(addr, cnt) \
    asm volatile("mbarrier.init.shared.b64 [%0], %1;" :: "r"((uint32_t)(addr)), "r"((uint32_t)(cnt)) : "memory")

#define MBARRIER_EXPECT_TX(addr, bytes) \
    asm volatile("mbarrier.arrive.expect_tx.shared.b64 _, [%0], %1;" \
        :: "r"((uint32_t)(addr)), "r"((uint32_t)(bytes)) : "memory")

#define MBARRIER_ARRIVE(addr) \
    asm volatile("mbarrier.arrive.shared.b64 _, [%0];" :: "r"((uint32_t)(addr)) : "memory")

#define MBARRIER_WAIT_PARITY(mbar_smem_addr, phase_parity) do { \
    uint32_t _mbar = (uint32_t)(mbar_smem_addr); \
    uint32_t _parity = (uint32_t)(phase_parity); \
    uint32_t _done; \
    asm volatile("{\n\t.reg .pred p;\n\t" \
        "mbarrier.try_wait.parity.acquire.cta.shared::cta.b64 p, [%1], %2;\n\t" \
        "selp.b32 %0, 1, 0, p;\n\t}" \
        : "=r"(_done) : "r"(_mbar), "r"(_parity) : "memory"); \
    if (!_done) { \
        asm volatile("{\n\t.reg .pred P1;\n\t" \
            "WAIT_LOOP_%=:\n\t" \
            "mbarrier.try_wait.parity.acquire.cta.shared::cta.b64 P1, [%0], %1, 0x989680;\n\t" \
            "@P1 bra.uni WAIT_DONE_%=;\n\t" \
            "bra.uni WAIT_LOOP_%=;\n\t" \
            "WAIT_DONE_%=:\n\t}" \
            :: "r"(_mbar), "r"(_parity) : "memory"); \
    } \
} while(0)

__device__ __forceinline__ void mbarrier_inval(uint32_t a) {
    asm volatile("mbarrier.inval.shared.b64 [%0];" :: "r"(a) : "memory");
}

__device__ __forceinline__ void bulk_g2s(uint32_t dst, const void* src,
                                         uint32_t bytes, uint32_t mbar) {
    asm volatile(
        "cp.async.bulk.shared::cluster.global.mbarrier::complete_tx::bytes "
        "[%0], [%1], %2, [%3];"
        :: "r"(dst), "l"(src), "r"(bytes), "r"(mbar) : "memory");
}

// half-CTA barrier for one m-group (4 warps = 128 threads), ids 1 and 2
#define GROUP_BAR(grp) \
    asm volatile("bar.sync %0, %1;" :: "r"((grp) + 1), "r"(128) : "memory")

__device__ __forceinline__ void ldsm4(uint32_t* r, uint32_t a) {
    asm volatile("ldmatrix.sync.aligned.m8n8.x4.shared.b16 {%0,%1,%2,%3}, [%4];"
        : "=r"(r[0]), "=r"(r[1]), "=r"(r[2]), "=r"(r[3]) : "r"(a));
}
__device__ __forceinline__ void ldsm4t(uint32_t* r, uint32_t a) {
    asm volatile("ldmatrix.sync.aligned.m8n8.x4.trans.shared.b16 {%0,%1,%2,%3}, [%4];"
        : "=r"(r[0]), "=r"(r[1]), "=r"(r[2]), "=r"(r[3]) : "r"(a));
}

__device__ __forceinline__ void mma16816(float* d, const uint32_t* a, const uint32_t* b) {
    asm volatile("mma.sync.aligned.m16n8k16.row.col.f32.f16.f16.f32 "
        "{%0,%1,%2,%3}, {%4,%5,%6,%7}, {%8,%9}, {%0,%1,%2,%3};"
        : "+f"(d[0]), "+f"(d[1]), "+f"(d[2]), "+f"(d[3])
        : "r"(a[0]), "r"(a[1]), "r"(a[2]), "r"(a[3]), "r"(b[0]), "r"(b[1]));
}

// ---------------- activations ----------------
// exact-ish f32 sigmoid (2 MUFU): S0 prologue only
__device__ __forceinline__ float sigf(float v) {
    float e, r;
    asm("ex2.approx.f32 %0, %1;" : "=f"(e) : "f"(-1.4426950408889634f * v));
    asm("rcp.approx.f32 %0, %1;" : "=f"(r) : "f"(1.0f + e));
    return r;
}
// 1-MUFU f32 tanh (err ~1e-4, damped by (1-G)) for H
__device__ __forceinline__ float tanhf1(float v) {
    float y; asm("tanh.approx.f32 %0, %1;" : "=f"(y) : "f"(v)); return y;
}
// f16x2 sigmoid: sigma(x) = 0.5*tanh(x/2) + 0.5  (1 MUFU per 2 values)
__device__ __forceinline__ __half2 sig_h2(__half2 v) {
    const __half2 h05 = __half2half2(__float2half_rn(0.5f));
    __half2 xh = __hmul2(v, h05);
    uint32_t t;
    asm("tanh.approx.f16x2 %0, %1;" : "=r"(t) : "r"(*(uint32_t*)&xh));
    return __hfma2(*(__half2*)&t, h05, h05);
}
__device__ __forceinline__ uint32_t h2u(__half2 h) { return *(uint32_t*)&h; }
__device__ __forceinline__ __half2 u2h(uint32_t u) { return *(__half2*)&u; }

// ============================================================================
// prep kernel: fp16 B images. img[G][k][n], stride 136 halves.
// gate order per layer: Z, G, R, H. k<128: W[L][k][n]; 128..135: U; 136: b.
// ============================================================================
__global__ void prep_kernel(
    const float* __restrict__ Uz, const float* __restrict__ Wz, const float* __restrict__ bz,
    const float* __restrict__ Ug, const float* __restrict__ Wg, const float* __restrict__ bg,
    const float* __restrict__ Ur, const float* __restrict__ Wr, const float* __restrict__ br,
    const float* __restrict__ Uh, const float* __restrict__ Wh, const float* __restrict__ bh)
{
    int t = blockIdx.x * blockDim.x + threadIdx.x;
    if (t >= 12 * GATE_HALVES) return;
    int G = t / GATE_HALVES;
    int rem = t % GATE_HALVES;
    int k = rem / 136;
    int n = rem % 136;
    int L = G >> 2, g = G & 3;
    float val = 0.0f;
    if (n < 128) {
        const float* W = (g == 0) ? Wz : (g == 1) ? Wg : (g == 2) ? Wr : Wh;
        const float* U = (g == 0) ? Uz : (g == 1) ? Ug : (g == 2) ? Ur : Uh;
        const float* bb = (g == 0) ? bz : (g == 1) ? bg : (g == 2) ? br : bh;
        if (k < 128)       val = W[L * 16384 + k * 128 + n];
        else if (k < 136)  val = U[L * 1024 + (k - 128) * 128 + n];
        else if (k == 136) val = bb[L * 128 + n];
    }
    *reinterpret_cast<__half*>(g_wimg + (size_t)G * GATE_BYTES + (size_t)k * 272 + (size_t)n * 2)
        = __float2half_rn(val);
}

// ============================================================================
// main fused kernel: 4096 CTAs x 256 threads, 2 CTAs/SM
// ============================================================================
__global__ void __launch_bounds__(256, 2)
dgm_kernel(const float* __restrict__ x,
           const float* __restrict__ Sw_w, const float* __restrict__ Sw_b,
           const float* __restrict__ Wf_w, const float* __restrict__ Wf_b,
           float* __restrict__ out)
{
    extern __shared__ __align__(1024) char smem[];
    const uint32_t sb = smem_to_u32(smem);
    const int tid  = threadIdx.x;
    const int lane = tid & 31;
    const int wid  = tid >> 5;
    const int mgrp = wid & 1;
    const int m0 = mgrp * 32;
    const int n0 = (wid >> 1) * 32;

    float* outs = (float*)(smem + OFF_OUTS);
    float* wf   = (float*)(smem + OFF_WF);
    float* sw   = (float*)(smem + OFF_SW);
    float* swb  = (float*)(smem + OFF_SWB);

    if (tid == 0) {
        MBARRIER_INIT(sb + OFF_MBAR,     1);
        MBARRIER_INIT(sb + OFF_MBAR + 8, 1);
        MBARRIER_INIT(sb + OFF_CONS,     8);   // one arrive per warp
        MBARRIER_INIT(sb + OFF_CONS + 8, 8);
        wf[128] = Wf_b[0];
    }
    if (tid < 128) { wf[tid] = Wf_w[tid]; swb[tid] = Sw_b[tid]; }
    if (tid < 64)  outs[tid] = 0.0f;
    ((float4*)sw)[tid] = ((const float4*)Sw_w)[tid];   // 4KB
    __syncthreads();

    // kick first two gate-weight loads
    if (tid == 0) {
        MBARRIER_EXPECT_TX(sb + OFF_MBAR, GATE_BYTES);
        bulk_g2s(sb + OFF_SLOT0, g_wimg, GATE_BYTES, sb + OFF_MBAR);
        MBARRIER_EXPECT_TX(sb + OFF_MBAR + 8, GATE_BYTES);
        bulk_g2s(sb + OFF_SLOT1, g_wimg + GATE_BYTES, GATE_BYTES, sb + OFF_MBAR + 8);
    }

    // ---------- S0 = sigmoid(x @ Sw + Sw_b), write A tile + ext ----------
    // r = tid&63, ch = tid>>6: warp-uniform ch -> sw/swb LDS are broadcasts,
    // x loads lane-consecutive (R13, the 100us win).
    {
        const int r  = tid & 63;
        const int ch = tid >> 6;
        const float* xr = x + ((size_t)blockIdx.x * 64 + r) * 8;
        float4 xa = *(const float4*)xr;
        float4 xb = *(const float4*)(xr + 4);
        char* arow = smem + OFF_A + (size_t)r * 304;
        if (ch == 0) {
            *(__half2*)(arow + (128 + 0)  * 2) = __floats2half2_rn(xa.x, xa.y);
            *(__half2*)(arow + (128 + 2)  * 2) = __floats2half2_rn(xa.z, xa.w);
            *(__half2*)(arow + (128 + 4)  * 2) = __floats2half2_rn(xb.x, xb.y);
            *(__half2*)(arow + (128 + 6)  * 2) = __floats2half2_rn(xb.z, xb.w);
            *(__half2*)(arow + (128 + 8)  * 2) = __floats2half2_rn(1.0f, 0.0f);
            *(__half2*)(arow + (128 + 10) * 2) = __floats2half2_rn(0.0f, 0.0f);
            *(__half2*)(arow + (128 + 12) * 2) = __floats2half2_rn(0.0f, 0.0f);
            *(__half2*)(arow + (128 + 14) * 2) = __floats2half2_rn(0.0f, 0.0f);
        }
#pragma unroll 4
        for (int i = 0; i < 16; i++) {
            int c = ch * 32 + 2 * i;
            float s0 = swb[c], s1 = swb[c + 1];
            s0 += xa.x * sw[0 * 128 + c] + xa.y * sw[1 * 128 + c]
                + xa.z * sw[2 * 128 + c] + xa.w * sw[3 * 128 + c]
                + xb.x * sw[4 * 128 + c] + xb.y * sw[5 * 128 + c]
                + xb.z * sw[6 * 128 + c] + xb.w * sw[7 * 128 + c];
            s1 += xa.x * sw[0 * 128 + c + 1] + xa.y * sw[1 * 128 + c + 1]
                + xa.z * sw[2 * 128 + c + 1] + xa.w * sw[3 * 128 + c + 1]
                + xb.x * sw[4 * 128 + c + 1] + xb.y * sw[5 * 128 + c + 1]
                + xb.z * sw[6 * 128 + c + 1] + xb.w * sw[7 * 128 + c + 1];
            *(__half2*)(arow + c * 2) = __floats2half2_rn(sigf(s0), sigf(s1));
        }
    }
    __syncthreads();

    // per-lane ldmatrix address bases
    const uint32_t aAddr = sb + OFF_A + (uint32_t)(m0 + (lane & 15)) * 304u
                         + (uint32_t)(lane >> 4) * 16u;
    const uint32_t bOff = (uint32_t)(lane & 15) * 272u
                        + (uint32_t)(n0 + (lane >> 4) * 8) * 2u;

    // register stage buffers: [mt*4+nt]
    uint32_t zstA[8], zstB[8], gstA[8], gstB[8];
    float pOut[2][2] = {{0.f, 0.f}, {0.f, 0.f}};

#pragma unroll 1
    for (int G = 0; G < 12; G++) {
        const int g = G & 3;
        const int L = G >> 2;
        const int slot = G & 1;
        const uint32_t slotB = sb + (slot ? OFF_SLOT1 : OFF_SLOT0);

        MBARRIER_WAIT_PARITY(sb + OFF_MBAR + slot * 8, (G >> 1) & 1);

        float acc[2][4][4];
#pragma unroll
        for (int i = 0; i < 2; i++)
#pragma unroll
            for (int j = 0; j < 4; j++)
#pragma unroll
                for (int v = 0; v < 4; v++) acc[i][j][v] = 0.0f;

#pragma unroll
        for (int ks = 0; ks < 9; ks++) {
            uint32_t a0[4], a1[4];
            ldsm4(a0, aAddr + (uint32_t)ks * 32u);
            ldsm4(a1, aAddr + 16u * 304u + (uint32_t)ks * 32u);
#pragma unroll
            for (int p = 0; p < 2; p++) {
                uint32_t b[4];
                ldsm4t(b, slotB + bOff + (uint32_t)ks * 4352u + (uint32_t)p * 32u);
                mma16816(acc[0][2 * p],     a0, b);
                mma16816(acc[0][2 * p + 1], a0, b + 2);
                mma16816(acc[1][2 * p],     a1, b);
                mma16816(acc[1][2 * p + 1], a1, b + 2);
            }
        }

        // slot consumed by this warp
        __syncwarp();
        if (lane == 0) MBARRIER_ARRIVE(sb + OFF_CONS + slot * 8);

        // producer: refill this slot with gate G+2 after all 8 warps consumed
        if (tid == 0 && G < 10) {
            MBARRIER_WAIT_PARITY(sb + OFF_CONS + slot * 8, (G >> 1) & 1);
            MBARRIER_EXPECT_TX(sb + OFF_MBAR + slot * 8, GATE_BYTES);
            bulk_g2s(slotB, g_wimg + (size_t)(G + 2) * GATE_BYTES, GATE_BYTES,
                     sb + OFF_MBAR + slot * 8);
        }

        // ---------------- per-gate epilogue ----------------
        if (g == 0) {
            // zst = sig(Z) * sigS  (reads A only, no barrier needed)
#pragma unroll
            for (int mt = 0; mt < 2; mt++) {
#pragma unroll
                for (int nt = 0; nt < 4; nt++) {
                    float* a4 = acc[mt][nt];
                    const int idx  = mt * 4 + nt;
                    const int rowA = m0 + mt * 16 + (lane >> 2);
                    const int col  = n0 + nt * 8 + (lane & 3) * 2;
                    char* aA = smem + OFF_A + (size_t)rowA * 304 + (size_t)col * 2;
                    char* aB = aA + 8 * 304;
                    __half2 sA = *(__half2*)aA, sB = *(__half2*)aB;
                    zstA[idx] = h2u(__hmul2(sig_h2(__floats2half2_rn(a4[0], a4[1])), sA));
                    zstB[idx] = h2u(__hmul2(sig_h2(__floats2half2_rn(a4[2], a4[3])), sB));
                }
            }
        } else if (g == 1) {
            // gst = sig(G)  (register-only)
#pragma unroll
            for (int mt = 0; mt < 2; mt++) {
#pragma unroll
                for (int nt = 0; nt < 4; nt++) {
                    float* a4 = acc[mt][nt];
                    const int idx = mt * 4 + nt;
                    gstA[idx] = h2u(sig_h2(__floats2half2_rn(a4[0], a4[1])));
                    gstB[idx] = h2u(sig_h2(__floats2half2_rn(a4[2], a4[3])));
                }
            }
        } else if (g == 2) {
            // A <- sigS * sig(R): precompute sig(R) BEFORE the barrier
            __half2 rA[8], rB[8];
#pragma unroll
            for (int mt = 0; mt < 2; mt++) {
#pragma unroll
                for (int nt = 0; nt < 4; nt++) {
                    float* a4 = acc[mt][nt];
                    const int idx = mt * 4 + nt;
                    rA[idx] = sig_h2(__floats2half2_rn(a4[0], a4[1]));
                    rB[idx] = sig_h2(__floats2half2_rn(a4[2], a4[3]));
                }
            }
            GROUP_BAR(mgrp);   // m-group's A reads (MMA) done
#pragma unroll
            for (int mt = 0; mt < 2; mt++) {
#pragma unroll
                for (int nt = 0; nt < 4; nt++) {
                    const int idx  = mt * 4 + nt;
                    const int rowA = m0 + mt * 16 + (lane >> 2);
                    const int col  = n0 + nt * 8 + (lane & 3) * 2;
                    char* aA = smem + OFF_A + (size_t)rowA * 304 + (size_t)col * 2;
                    char* aB = aA + 8 * 304;
                    *(__half2*)aA = __hmul2(rA[idx], *(__half2*)aA);
                    *(__half2*)aB = __hmul2(rB[idx], *(__half2*)aB);
                }
            }
            GROUP_BAR(mgrp);   // A2 visible before H's MMA reads
        } else if (L < 2) {
            // S' = (1-sigG)*tanh(H) + zst, then sigmoid — ALL register work
            // hoisted above the barrier; only the stores sit between bars.
            __half2 oA[8], oB[8];
#pragma unroll
            for (int mt = 0; mt < 2; mt++) {
#pragma unroll
                for (int nt = 0; nt < 4; nt++) {
                    float* a4 = acc[mt][nt];
                    const int idx = mt * 4 + nt;
                    __half2 zzA = u2h(zstA[idx]), zzB = u2h(zstB[idx]);
                    __half2 ggA = u2h(gstA[idx]), ggB = u2h(gstB[idx]);
                    float sp0 = (1.0f - __low2float(ggA))  * tanhf1(a4[0]) + __low2float(zzA);
                    float sp1 = (1.0f - __high2float(ggA)) * tanhf1(a4[1]) + __high2float(zzA);
                    float sp2 = (1.0f - __low2float(ggB))  * tanhf1(a4[2]) + __low2float(zzB);
                    float sp3 = (1.0f - __high2float(ggB)) * tanhf1(a4[3]) + __high2float(zzB);
                    oA[idx] = sig_h2(__floats2half2_rn(sp0, sp1));
                    oB[idx] = sig_h2(__floats2half2_rn(sp2, sp3));
                }
            }
            GROUP_BAR(mgrp);   // m-group's A2 reads (H MMA) done
#pragma unroll
            for (int mt = 0; mt < 2; mt++) {
#pragma unroll
                for (int nt = 0; nt < 4; nt++) {
                    const int idx  = mt * 4 + nt;
                    const int rowA = m0 + mt * 16 + (lane >> 2);
                    const int col  = n0 + nt * 8 + (lane & 3) * 2;
                    char* aA = smem + OFF_A + (size_t)rowA * 304 + (size_t)col * 2;
                    *(__half2*)aA = oA[idx];
                    *(__half2*)(aA + 8 * 304) = oB[idx];
                }
            }
            GROUP_BAR(mgrp);   // S' visible before next layer's MMA reads
        } else {
            // last layer: fold into output dot product (no A writes)
#pragma unroll
            for (int mt = 0; mt < 2; mt++) {
#pragma unroll
                for (int nt = 0; nt < 4; nt++) {
                    float* a4 = acc[mt][nt];
                    const int idx = mt * 4 + nt;
                    const int col = n0 + nt * 8 + (lane & 3) * 2;
                    __half2 zzA = u2h(zstA[idx]), zzB = u2h(zstB[idx]);
                    __half2 ggA = u2h(gstA[idx]), ggB = u2h(gstB[idx]);
                    float sp0 = (1.0f - __low2float(ggA))  * tanhf1(a4[0]) + __low2float(zzA);
                    float sp1 = (1.0f - __high2float(ggA)) * tanhf1(a4[1]) + __high2float(zzA);
                    float sp2 = (1.0f - __low2float(ggB))  * tanhf1(a4[2]) + __low2float(zzB);
                    float sp3 = (1.0f - __high2float(ggB)) * tanhf1(a4[3]) + __high2float(zzB);
                    pOut[mt][0] += sp0 * wf[col] + sp1 * wf[col + 1];
                    pOut[mt][1] += sp2 * wf[col] + sp3 * wf[col + 1];
                }
            }
        }
    }

    // ---------------- final reduction: out = S' @ Wf + b ----------------
#pragma unroll
    for (int mt = 0; mt < 2; mt++) {
#pragma unroll
        for (int ab = 0; ab < 2; ab++) {
            float v = pOut[mt][ab];
            v += __shfl_xor_sync(0xffffffffu, v, 1);
            v += __shfl_xor_sync(0xffffffffu, v, 2);
            if ((lane & 3) == 0) {
                int row = m0 + mt * 16 + (lane >> 2) + ab * 8;
                atomicAdd(outs + row, v);
            }
        }
    }
    __syncthreads();
    if (tid < 64)
        out[(size_t)blockIdx.x * 64 + tid] = outs[tid] + wf[128];

    if (tid == 0) {
        mbarrier_inval(sb + OFF_MBAR);
        mbarrier_inval(sb + OFF_MBAR + 8);
        mbarrier_inval(sb + OFF_CONS);
        mbarrier_inval(sb + OFF_CONS + 8);
    }
}

// ============================================================================
extern "C" void kernel_launch(void* const* d_in, const int* in_sizes, int n_in,
                              void* d_out, int out_size) {
    (void)in_sizes; (void)n_in; (void)out_size;
    const float* x     = (const float*)d_in[0];
    const float* Sw_w  = (const float*)d_in[1];
    const float* Sw_b  = (const float*)d_in[2];
    const float* Uz    = (const float*)d_in[3];
    const float* Wsz_w = (const float*)d_in[4];
    const float* Wsz_b = (const float*)d_in[5];
    const float* Ug    = (const float*)d_in[6];
    const float* Wsg_w = (const float*)d_in[7];
    const float* Wsg_b = (const float*)d_in[8];
    const float* Ur    = (const float*)d_in[9];
    const float* Wsr_w = (const float*)d_in[10];
    const float* Wsr_b = (const float*)d_in[11];
    const float* Uh    = (const float*)d_in[12];
    const float* Wsh_w = (const float*)d_in[13];
    const float* Wsh_b = (const float*)d_in[14];
    const float* Wf_w  = (const float*)d_in[15];
    const float* Wf_b  = (const float*)d_in[16];
    float* out = (float*)d_out;

    cudaFuncSetAttribute(dgm_kernel, cudaFuncAttributeMaxDynamicSharedMemorySize,
                         SMEM_TOTAL);

    prep_kernel<<<918, 256>>>(Uz, Wsz_w, Wsz_b, Ug, Wsg_w, Wsg_b,
                              Ur, Wsr_w, Wsr_b, Uh, Wsh_w, Wsh_b);
    dgm_kernel<<<4096, 256, SMEM_TOTAL>>>(x, Sw_w, Sw_b, Wf_w, Wf_b, out);
}